// round 9
// baseline (speedup 1.0000x reference)
#include <cuda_runtime.h>

#define TCOLS 4096
#define BROWS 4096
#define NT 256
#define NWARP 8
#define NCTA 1024          // 8192 warp-tasks / 8 warps per CTA
#define FULL 0xffffffffu

__device__ float2   g_resP[BROWS];   // {sbp, dbp} per preds row
__device__ float2   g_resL[BROWS];   // {sbp, dbp} per labels row
__device__ unsigned g_done;          // zero-init; reset by last CTA each launch

__device__ __forceinline__ float warp_sum(float v) {
    #pragma unroll
    for (int o = 16; o; o >>= 1) v += __shfl_xor_sync(FULL, v, o);
    return v;
}

__global__ __launch_bounds__(NT, 5)
void pv_warp_kernel(const float* __restrict__ preds,
                    const float* __restrict__ labels,
                    float* __restrict__ out) {
    __shared__ unsigned smask[8][NT];   // per-thread packed masks: pk lo16 | vy hi16
    __shared__ float    red[NWARP];
    __shared__ bool     amLast;

    const int tid  = threadIdx.x;
    const int lane = tid & 31;
    const int wid  = tid >> 5;
    const int task = blockIdx.x * NWARP + wid;   // 0..8191
    const int arr  = task >> 12;                 // 0 = preds, 1 = labels
    const int row  = task & (BROWS - 1);

    const float* rowp = (arr ? labels : preds) + ((size_t)row << 12);
    const float4* g   = (const float4*)rowp;

    // ---- Pass 1: stream 32 float4 groups (depth-2), build masks in SMEM ----
    float psum = 0.f, vsum = 0.f;
    int   pcnt = 0,   vcnt = 0;

    float4 cur = g[lane];
    float carry = __shfl_sync(FULL, cur.x, 0);   // row start: d0 = 0 (excluded)

    for (int w = 0; w < 8; ++w) {
        unsigned mword = 0;
        #pragma unroll
        for (int gi = 0; gi < 4; ++gi) {
            const int j = w * 4 + gi;            // group index 0..31
            float4 nxt = cur;
            if (j < 31) nxt = g[(j + 1) * 32 + lane];
            float lead = (j < 31) ? __shfl_sync(FULL, nxt.x, 0)
                                  : __shfl_sync(FULL, cur.w, 31);  // row end: d=0
            float lv = __shfl_up_sync(FULL, cur.w, 1);
            if (lane == 0) lv = carry;
            float rv = __shfl_down_sync(FULL, cur.x, 1);
            if (lane == 31) rv = lead;
            carry = __shfl_sync(FULL, cur.w, 31);

            float d0 = cur.x - lv, d1 = cur.y - cur.x, d2 = cur.z - cur.y,
                  d3 = cur.w - cur.z, d4 = rv - cur.w;

            if (fminf(d0, -d1) > 0.f) { psum += cur.x; mword |= 1u << (gi * 4 + 0); }
            if (fmaxf(d0, -d1) < 0.f) { vsum += cur.x; mword |= 1u << (16 + gi * 4 + 0); }
            if (fminf(d1, -d2) > 0.f) { psum += cur.y; mword |= 1u << (gi * 4 + 1); }
            if (fmaxf(d1, -d2) < 0.f) { vsum += cur.y; mword |= 1u << (16 + gi * 4 + 1); }
            if (fminf(d2, -d3) > 0.f) { psum += cur.z; mword |= 1u << (gi * 4 + 2); }
            if (fmaxf(d2, -d3) < 0.f) { vsum += cur.z; mword |= 1u << (16 + gi * 4 + 2); }
            if (fminf(d3, -d4) > 0.f) { psum += cur.w; mword |= 1u << (gi * 4 + 3); }
            if (fmaxf(d3, -d4) < 0.f) { vsum += cur.w; mword |= 1u << (16 + gi * 4 + 3); }

            cur = nxt;
        }
        smask[w][tid] = mword;
        pcnt += __popc(mword & 0xFFFFu);
        vcnt += __popc(mword >> 16);
    }

    psum = warp_sum(psum);
    vsum = warp_sum(vsum);
    pcnt = __reduce_add_sync(FULL, pcnt);
    vcnt = __reduce_add_sync(FULL, vcnt);
    const float pm = psum / (float)pcnt;
    const float vm = vsum / (float)vcnt;

    // ---- Pass 2: reload row (L2-hot), thresholded masked means ----
    float s0 = 0.f, s1 = 0.f;
    int   c0 = 0,   c1 = 0;

    for (int w = 0; w < 8; ++w) {
        const unsigned mword = smask[w][tid];
        #pragma unroll
        for (int gi = 0; gi < 4; ++gi) {
            const int j = w * 4 + gi;
            float4 a = g[j * 32 + lane];
            if ((mword & (1u << (gi * 4 + 0)))      && a.x >= pm) { s0 += a.x; c0++; }
            if ((mword & (1u << (16 + gi * 4 + 0))) && a.x <= vm) { s1 += a.x; c1++; }
            if ((mword & (1u << (gi * 4 + 1)))      && a.y >= pm) { s0 += a.y; c0++; }
            if ((mword & (1u << (16 + gi * 4 + 1))) && a.y <= vm) { s1 += a.y; c1++; }
            if ((mword & (1u << (gi * 4 + 2)))      && a.z >= pm) { s0 += a.z; c0++; }
            if ((mword & (1u << (16 + gi * 4 + 2))) && a.z <= vm) { s1 += a.z; c1++; }
            if ((mword & (1u << (gi * 4 + 3)))      && a.w >= pm) { s0 += a.w; c0++; }
            if ((mword & (1u << (16 + gi * 4 + 3))) && a.w <= vm) { s1 += a.w; c1++; }
        }
    }

    s0 = warp_sum(s0);
    s1 = warp_sum(s1);
    c0 = __reduce_add_sync(FULL, c0);
    c1 = __reduce_add_sync(FULL, c1);

    if (lane == 0) {
        float2 r = make_float2(s0 / (float)c0, s1 / (float)c1);
        if (arr) g_resL[row] = r; else g_resP[row] = r;
    }

    // ---- Grid finish: last CTA combines all per-row results ----
    __syncthreads();
    if (tid == 0) {
        __threadfence();
        amLast = (atomicAdd(&g_done, 1u) == (unsigned)(NCTA - 1));
    }
    __syncthreads();

    if (amLast) {
        float acc = 0.f;
        #pragma unroll
        for (int q = 0; q < BROWS / NT; ++q) {
            int r = tid + q * NT;
            float2 p = g_resP[r];
            float2 l = g_resL[r];
            float d0 = p.x - l.x;
            float d1 = p.y - l.y;
            acc += d0 * d0 + d1 * d1;
        }
        acc = warp_sum(acc);
        if (lane == 0) red[wid] = acc;
        __syncthreads();
        if (tid == 0) {
            float t = 0.f;
            #pragma unroll
            for (int w = 0; w < NWARP; ++w) t += red[w];
            out[0] = t / (float)(BROWS * 2);
            g_done = 0;
        }
    }
}

extern "C" void kernel_launch(void* const* d_in, const int* in_sizes, int n_in,
                              void* d_out, int out_size) {
    const float* preds  = (const float*)d_in[0];
    const float* labels = (const float*)d_in[1];
    pv_warp_kernel<<<NCTA, NT>>>(preds, labels, (float*)d_out);
}

// round 10
// speedup vs baseline: 1.4489x; 1.4489x over previous
#include <cuda_runtime.h>

#define TCOLS 4096
#define BROWS 4096
#define NT 128
#define NWARP 4
#define NCTA (2 * BROWS)
#define FULL 0xffffffffu

__device__ float2   g_resP[BROWS];   // {sbp, dbp} per preds row
__device__ float2   g_resL[BROWS];   // {sbp, dbp} per labels row
__device__ unsigned g_done;          // zero-init; reset by last CTA

__device__ __forceinline__ float warp_sum(float v) {
    #pragma unroll
    for (int o = 16; o; o >>= 1) v += __shfl_xor_sync(FULL, v, o);
    return v;
}

__global__ __launch_bounds__(NT, 8)
void pv_kernel(const float* __restrict__ preds,
               const float* __restrict__ labels,
               float* __restrict__ out) {
    __shared__ float sred[4][NWARP];
    __shared__ bool  amLast;

    const int tid  = threadIdx.x;
    const int lane = tid & 31;
    const int wid  = tid >> 5;
    const int arr  = blockIdx.x >> 12;          // 0 = preds, 1 = labels
    const int row  = blockIdx.x & (BROWS - 1);

    const float* rowp = (arr ? labels : preds) + ((size_t)row << 12);
    const int wb = wid << 10;                   // 1024 elements per warp
    const float4* g4 = (const float4*)(rowp + wb);

    // ---- Load lane's 32 elements (8 coalesced float4 groups) ----
    float v[32];
    #pragma unroll
    for (int g = 0; g < 8; g++) {
        float4 a = g4[g * 32 + lane];
        v[4*g] = a.x; v[4*g+1] = a.y; v[4*g+2] = a.z; v[4*g+3] = a.w;
    }

    // Segment-edge values (clamped duplicates at row ends -> d==0 -> excluded).
    float edge_l = 0.f, edge_r = 0.f;
    if (lane == 31) edge_l = rowp[wb ? wb - 1 : 0];
    if (lane == 0)  edge_r = rowp[wb + 1024 < TCOLS ? wb + 1024 : TCOLS - 1];

    const int upidx = (lane + 31) & 31;
    const int dnidx = (lane + 1) & 31;
    const bool is31 = (lane == 31);
    const bool is0  = (lane == 0);

    // ---- Pass 1: peak/valley detect; 2 shuffles per group via blend-rotate ----
    float psum = 0.f, vsum = 0.f;
    unsigned pkm = 0, vym = 0;
    float prevw = edge_l;                       // consumed from lane 31 only
    #pragma unroll
    for (int g = 0; g < 8; g++) {
        const float cx = v[4*g], cy = v[4*g+1], cz = v[4*g+2], cw = v[4*g+3];
        float bl = is31 ? prevw : cw;
        float lv = __shfl_sync(FULL, bl, upidx);     // lane i <- lane i-1 (wrap)
        float nx = (g < 7) ? v[4*g+4] : edge_r;
        float br = is0 ? nx : cx;
        float rv = __shfl_sync(FULL, br, dnidx);     // lane i <- lane i+1 (wrap)
        prevw = cw;

        float d0 = cx - lv, d1 = cy - cx, d2 = cz - cy, d3 = cw - cz, d4 = rv - cw;
        float e[4]  = {cx, cy, cz, cw};
        float dd[5] = {d0, d1, d2, d3, d4};
        #pragma unroll
        for (int k = 0; k < 4; k++) {
            if (fminf(dd[k], -dd[k+1]) > 0.f) { psum += e[k]; pkm |= 1u << (4*g + k); }
            if (fmaxf(dd[k], -dd[k+1]) < 0.f) { vsum += e[k]; vym |= 1u << (4*g + k); }
        }
    }

    psum = warp_sum(psum);
    vsum = warp_sum(vsum);
    int pcnt = __reduce_add_sync(FULL, __popc(pkm));
    int vcnt = __reduce_add_sync(FULL, __popc(vym));
    if (lane == 0) {
        sred[0][wid] = psum;
        sred[1][wid] = vsum;
        sred[2][wid] = (float)pcnt;
        sred[3][wid] = (float)vcnt;
    }
    __syncthreads();
    const float pm = (sred[0][0] + sred[0][1] + sred[0][2] + sred[0][3])
                   / (sred[2][0] + sred[2][1] + sred[2][2] + sred[2][3]);
    const float vm = (sred[1][0] + sred[1][1] + sred[1][2] + sred[1][3])
                   / (sred[3][0] + sred[3][1] + sred[3][2] + sred[3][3]);
    __syncthreads();   // sred reuse

    // ---- Pass 2: thresholded masked means, registers only; float counts ----
    float s0 = 0.f, s1 = 0.f, c0 = 0.f, c1 = 0.f;
    #pragma unroll
    for (int k = 0; k < 32; k++) {
        const unsigned bit = 1u << k;
        if ((pkm & bit) && v[k] >= pm) { s0 += v[k]; c0 += 1.f; }
        if ((vym & bit) && v[k] <= vm) { s1 += v[k]; c1 += 1.f; }
    }
    s0 = warp_sum(s0);
    s1 = warp_sum(s1);
    c0 = warp_sum(c0);
    c1 = warp_sum(c1);
    if (lane == 0) {
        sred[0][wid] = s0;
        sred[1][wid] = s1;
        sred[2][wid] = c0;
        sred[3][wid] = c1;
    }
    __syncthreads();

    if (tid == 0) {
        float a0 = sred[0][0] + sred[0][1] + sred[0][2] + sred[0][3];
        float a1 = sred[1][0] + sred[1][1] + sred[1][2] + sred[1][3];
        float a2 = sred[2][0] + sred[2][1] + sred[2][2] + sred[2][3];
        float a3 = sred[3][0] + sred[3][1] + sred[3][2] + sred[3][3];
        float2 r = make_float2(a0 / a2, a1 / a3);
        if (arr) g_resL[row] = r; else g_resP[row] = r;
        __threadfence();
        amLast = (atomicAdd(&g_done, 1u) == (unsigned)(NCTA - 1));
    }
    __syncthreads();

    // ---- Last CTA: combine all per-row results into the scalar loss ----
    if (amLast) {
        float acc = 0.f;
        #pragma unroll
        for (int q = 0; q < BROWS / NT; q++) {
            int r = tid + q * NT;
            float2 p = g_resP[r];
            float2 l = g_resL[r];
            float d0 = p.x - l.x;
            float d1 = p.y - l.y;
            acc += d0 * d0 + d1 * d1;
        }
        acc = warp_sum(acc);
        if (lane == 0) sred[0][wid] = acc;
        __syncthreads();
        if (tid == 0) {
            out[0] = (sred[0][0] + sred[0][1] + sred[0][2] + sred[0][3])
                   / (float)(BROWS * 2);
            g_done = 0;
        }
    }
}

extern "C" void kernel_launch(void* const* d_in, const int* in_sizes, int n_in,
                              void* d_out, int out_size) {
    const float* preds  = (const float*)d_in[0];
    const float* labels = (const float*)d_in[1];
    pv_kernel<<<NCTA, NT>>>(preds, labels, (float*)d_out);
}

// round 11
// speedup vs baseline: 1.5213x; 1.0500x over previous
#include <cuda_runtime.h>

#define TCOLS 4096
#define BROWS 4096
#define NT 128
#define NWARP 4
#define NCTA (2 * BROWS)
#define FULL 0xffffffffu

__device__ float2   g_resP[BROWS];   // {sbp, dbp} per preds row
__device__ float2   g_resL[BROWS];   // {sbp, dbp} per labels row
__device__ unsigned g_done;          // zero-init; reset by last CTA

__device__ __forceinline__ float warp_sum(float v) {
    #pragma unroll
    for (int o = 16; o; o >>= 1) v += __shfl_xor_sync(FULL, v, o);
    return v;
}

__global__ __launch_bounds__(NT, 8)
void pv_kernel(const float* __restrict__ preds,
               const float* __restrict__ labels,
               float* __restrict__ out) {
    __shared__ float sred[4][NWARP];
    __shared__ bool  amLast;

    const int tid  = threadIdx.x;
    const int lane = tid & 31;
    const int wid  = tid >> 5;
    const int arr  = blockIdx.x >> 12;          // 0 = preds, 1 = labels
    const int row  = blockIdx.x & (BROWS - 1);

    const float* rowp = (arr ? labels : preds) + ((size_t)row << 12);
    const int wb = wid << 10;                   // 1024 elements per warp
    const float4* g4 = (const float4*)(rowp + wb);

    // ---- Load lane's 32 elements (8 coalesced float4 groups) ----
    float v[32];
    #pragma unroll
    for (int g = 0; g < 8; g++) {
        float4 a = g4[g * 32 + lane];
        v[4*g] = a.x; v[4*g+1] = a.y; v[4*g+2] = a.z; v[4*g+3] = a.w;
    }

    // Segment-edge values (row-end centers are masked off explicitly below).
    float edge_l = 0.f, edge_r = 0.f;
    if (lane == 31) edge_l = rowp[wb ? wb - 1 : 0];
    if (lane == 0)  edge_r = rowp[wb + 1024 < TCOLS ? wb + 1024 : TCOLS - 1];

    const int upidx = (lane + 31) & 31;
    const int dnidx = (lane + 1) & 31;
    const bool is31 = (lane == 31);
    const bool is0  = (lane == 0);
    const bool rowStart = is0  && (wb == 0);
    const bool rowEnd   = is31 && (wb + 1024 == TCOLS);

    // ---- Pass 1: sign-packed peak/valley detection ----
    float psum = 0.f, vsum = 0.f;
    unsigned pkm = 0, vym = 0;
    float prevw = edge_l;
    #pragma unroll
    for (int g = 0; g < 8; g++) {
        const float cx = v[4*g], cy = v[4*g+1], cz = v[4*g+2], cw = v[4*g+3];
        float bl = is31 ? prevw : cw;
        float lv = __shfl_sync(FULL, bl, upidx);     // lane i <- lane i-1 value
        float nx = (g < 7) ? v[4*g+4] : edge_r;
        float br = is0 ? nx : cx;
        float rv = __shfl_sync(FULL, br, dnidx);     // lane i <- lane i+1 value
        prevw = cw;

        const int i0 = __float_as_int(cx - lv);
        const int i1 = __float_as_int(cy - cx);
        const int i2 = __float_as_int(cz - cy);
        const int i3 = __float_as_int(cw - cz);
        const int i4 = __float_as_int(rv - cw);

        // Pack sign bytes: s = [sb(d0),sb(d1),sb(d2),sb(d3)], sn = [sb(d1..d4)]
        unsigned a01 = __byte_perm(i0, i1, 0x0073);
        unsigned a23 = __byte_perm(i2, i3, 0x7300);
        unsigned s   = __byte_perm(a01, a23, 0x7610);
        unsigned sn  = __byte_perm(s,   i4, 0x7321);
        unsigned pkb = ~s & sn;      // bit7 of byte k: d_k>0 && d_{k+1}<0
        unsigned vyb = s & ~sn;      // bit7 of byte k: d_k<0 && d_{k+1}>0

        // Row-edge centers (cols 0 and TCOLS-1) are not valid centers.
        if (g == 0 && rowStart) { pkb &= ~0x80u;       vyb &= ~0x80u; }
        if (g == 7 && rowEnd)   { pkb &= 0x7fffffffu;  vyb &= 0x7fffffffu; }

        const float e[4] = {cx, cy, cz, cw};
        #pragma unroll
        for (int k = 0; k < 4; k++) {
            if (pkb & (0x80u << (8*k))) { psum += e[k]; pkm |= 1u << (4*g + k); }
            if (vyb & (0x80u << (8*k))) { vsum += e[k]; vym |= 1u << (4*g + k); }
        }
    }

    psum = warp_sum(psum);
    vsum = warp_sum(vsum);
    int pcnt = __reduce_add_sync(FULL, __popc(pkm));
    int vcnt = __reduce_add_sync(FULL, __popc(vym));
    if (lane == 0) {
        sred[0][wid] = psum;
        sred[1][wid] = vsum;
        sred[2][wid] = (float)pcnt;
        sred[3][wid] = (float)vcnt;
    }
    __syncthreads();
    const float pm = (sred[0][0] + sred[0][1] + sred[0][2] + sred[0][3])
                   / (sred[2][0] + sred[2][1] + sred[2][2] + sred[2][3]);
    const float vm = (sred[1][0] + sred[1][1] + sred[1][2] + sred[1][3])
                   / (sred[3][0] + sred[3][1] + sred[3][2] + sred[3][3]);
    __syncthreads();   // sred reuse

    // ---- Pass 2: thresholded masked means, registers only; float counts ----
    float s0 = 0.f, s1 = 0.f, c0 = 0.f, c1 = 0.f;
    #pragma unroll
    for (int k = 0; k < 32; k++) {
        const unsigned bit = 1u << k;
        if ((pkm & bit) && v[k] >= pm) { s0 += v[k]; c0 += 1.f; }
        if ((vym & bit) && v[k] <= vm) { s1 += v[k]; c1 += 1.f; }
    }
    s0 = warp_sum(s0);
    s1 = warp_sum(s1);
    c0 = warp_sum(c0);
    c1 = warp_sum(c1);
    if (lane == 0) {
        sred[0][wid] = s0;
        sred[1][wid] = s1;
        sred[2][wid] = c0;
        sred[3][wid] = c1;
    }
    __syncthreads();

    if (tid == 0) {
        float a0 = sred[0][0] + sred[0][1] + sred[0][2] + sred[0][3];
        float a1 = sred[1][0] + sred[1][1] + sred[1][2] + sred[1][3];
        float a2 = sred[2][0] + sred[2][1] + sred[2][2] + sred[2][3];
        float a3 = sred[3][0] + sred[3][1] + sred[3][2] + sred[3][3];
        float2 r = make_float2(a0 / a2, a1 / a3);
        if (arr) g_resL[row] = r; else g_resP[row] = r;
        __threadfence();
        amLast = (atomicAdd(&g_done, 1u) == (unsigned)(NCTA - 1));
    }
    __syncthreads();

    // ---- Last CTA: combine all per-row results into the scalar loss ----
    if (amLast) {
        float acc = 0.f;
        #pragma unroll
        for (int q = 0; q < BROWS / NT; q++) {
            int r = tid + q * NT;
            float2 p = g_resP[r];
            float2 l = g_resL[r];
            float d0 = p.x - l.x;
            float d1 = p.y - l.y;
            acc += d0 * d0 + d1 * d1;
        }
        acc = warp_sum(acc);
        if (lane == 0) sred[0][wid] = acc;
        __syncthreads();
        if (tid == 0) {
            out[0] = (sred[0][0] + sred[0][1] + sred[0][2] + sred[0][3])
                   / (float)(BROWS * 2);
            g_done = 0;
        }
    }
}

extern "C" void kernel_launch(void* const* d_in, const int* in_sizes, int n_in,
                              void* d_out, int out_size) {
    const float* preds  = (const float*)d_in[0];
    const float* labels = (const float*)d_in[1];
    pv_kernel<<<NCTA, NT>>>(preds, labels, (float*)d_out);
}